// round 17
// baseline (speedup 1.0000x reference)
#include <cuda_runtime.h>
#include <cuda_fp16.h>
#include <math.h>

#define N 4096
#define D 128
#define NB 32
#define ALPHA 10.0f
#define BETA 2.0f
#define BASE 0.5f
#define BIGF 1e30f
#define LOG2E 1.4426950408889634f

// ---------------- device scratch (static zero-init; no allocation allowed) ----------------
__device__ float         g_sim[(size_t)N * N];   // 64 MB similarity matrix
// FP16 hi/lo operand arrays in m16n8k16 fragment layout (verified R14):
//  A (m16 tiles, 8 k16-steps): slot = (t*8+s)*32+lane ; 4 half2 regs per slot
//  B (n8 tiles):               slot = (nt*8+s)*32+lane ; 2 half2 regs per slot
__device__ unsigned      g_Ah[(size_t)65536 * 4];
__device__ unsigned      g_Al[(size_t)65536 * 4];
__device__ unsigned      g_Bh[(size_t)131072 * 2];
__device__ unsigned      g_Bl[(size_t)131072 * 2];
// Encoded extrema with ZERO identity (idempotent across graph replays):
__device__ unsigned      g_eminpos[N];   // max of f2u(-sim) over positives; 0 => +BIGF
__device__ unsigned      g_emaxneg[N];   // max of f2u(+sim) over negatives; 0 => -BIGF
__device__ unsigned char g_t8[N];        // targets as uint8

__device__ __forceinline__ unsigned f2u(float f) {
    unsigned b = __float_as_uint(f);
    return (b & 0x80000000u) ? ~b : (b | 0x80000000u);
}
__device__ __forceinline__ float u2f(unsigned u) {
    return (u & 0x80000000u) ? __uint_as_float(u ^ 0x80000000u) : __uint_as_float(~u);
}
__device__ __forceinline__ float ex2(float x) {
    float r;
    asm("ex2.approx.f32 %0, %1;" : "=f"(r) : "f"(x));
    return r;
}
__device__ __forceinline__ unsigned pack_hilo(float x, float y, unsigned& loOut) {
    __half hx = __float2half_rn(x), hy = __float2half_rn(y);
    __half lx = __float2half_rn(x - __half2float(hx));
    __half ly = __float2half_rn(y - __half2float(hy));
    loOut = (unsigned)__half_as_ushort(lx) | ((unsigned)__half_as_ushort(ly) << 16);
    return (unsigned)__half_as_ushort(hx) | ((unsigned)__half_as_ushort(hy) << 16);
}
__device__ __forceinline__ void mma_f16(float* c, const uint4& a, const uint2& b) {
    asm volatile(
        "mma.sync.aligned.m16n8k16.row.col.f32.f16.f16.f32 "
        "{%0,%1,%2,%3}, {%4,%5,%6,%7}, {%8,%9}, {%0,%1,%2,%3};"
        : "+f"(c[0]), "+f"(c[1]), "+f"(c[2]), "+f"(c[3])
        : "r"(a.x), "r"(a.y), "r"(a.z), "r"(a.w), "r"(b.x), "r"(b.y));
}

// ---------------- k_cvt: one thread per fragment-register (max parallelism) ----------------
// blocks [0,1024): A regs (262144); [1024,2048): B regs (262144); block 2048: targets + out[0]
__global__ void k_cvt(const float* __restrict__ X, const int* __restrict__ tgt,
                      float* __restrict__ out, int out_size) {
    const int b = blockIdx.x, tid = threadIdx.x;
    if (b < 1024) {
        int f = b * 256 + tid;                 // A reg index = slot*4 + r
        int slot = f >> 2, r = f & 3;
        int t = slot >> 8, rem = slot & 255, s = rem >> 5, l = rem & 31;
        int g = l >> 2, q = l & 3;
        int mm = t * 16 + g + 8 * (r & 1);
        int kk = s * 16 + 2 * q + 8 * (r >> 1);
        float2 v = *reinterpret_cast<const float2*>(&X[mm * D + kk]);
        unsigned lo, hi = pack_hilo(v.x, v.y, lo);
        g_Ah[f] = hi;
        g_Al[f] = lo;
    } else if (b < 2048) {
        int f = (b - 1024) * 256 + tid;        // B reg index = slot*2 + r
        int slot = f >> 1, r = f & 1;
        int nt = slot >> 8, rem = slot & 255, s = rem >> 5, l = rem & 31;
        int g = l >> 2, q = l & 3;
        int n0 = nt * 8 + g;
        int kk = s * 16 + 2 * q + 8 * r;
        float2 v = *reinterpret_cast<const float2*>(&X[n0 * D + kk]);
        unsigned lo, hi = pack_hilo(v.x, v.y, lo);
        g_Bh[f] = hi;
        g_Bl[f] = lo;
    } else {
        __shared__ int sIs64;
        if (tid < 32) {
            int bad = 0;
            #pragma unroll
            for (int i = 0; i < 4; i++)
                if (tgt[1 + 2 * (tid + 32 * i)] != 0) bad = 1;
            unsigned ab = __ballot_sync(0xFFFFFFFFu, bad);
            if (tid == 0) sIs64 = (ab == 0);
        }
        if (tid == 0 && out_size >= 1) out[0] = 0.0f;
        __syncthreads();
        for (int j = tid; j < N; j += 256)
            g_t8[j] = sIs64 ? (unsigned char)((const long long*)tgt)[j]
                            : (unsigned char)tgt[j];
    }
}

// ---------------- k_gemm: sim = X X^T (2-term fp16 split, 3 passes), upper triangle ----------------
// Triangle-packed 528 blocks, 256 threads = 8 warps (2x4), warp tile 64x32. (verified R14)
__global__ __launch_bounds__(256, 2) void k_gemm() {
    __shared__ __align__(16) float sm[9216];   // epilogue staging only (8 x 1152)

    const int tid = threadIdx.x;

    const int lin = blockIdx.x;
    int bi = (int)(32.5f - sqrtf(32.5f * 32.5f - 2.0f * (float)lin));
    #define TRI_OFF(r) ((r) * NB - ((r) * ((r) - 1)) / 2)
    while (bi > 0 && TRI_OFF(bi) > lin) bi--;
    while (bi < NB - 1 && TRI_OFF(bi + 1) <= lin) bi++;
    const int bj = bi + (lin - TRI_OFF(bi));
    #undef TRI_OFF

    const int rowBase = bi * 128;
    const int colBase = bj * 128;

    const int w    = tid >> 5;
    const int lane = tid & 31;
    const int wr   = w >> 2;
    const int wc   = w & 3;
    const int g    = lane >> 2;
    const int q    = lane & 3;

    float c[4][4][4];
    #pragma unroll
    for (int mt = 0; mt < 4; mt++)
        #pragma unroll
        for (int nt = 0; nt < 4; nt++)
            #pragma unroll
            for (int r = 0; r < 4; r++) c[mt][nt][r] = 0.0f;

    const int aSlot0 = ((bi * 8 + wr * 4) * 8) * 32 + lane;
    const int bSlot0 = ((bj * 16 + wc * 4) * 8) * 32 + lane;

    #pragma unroll 2
    for (int s = 0; s < 8; s++) {
        uint4 ah[4], al[4];
        uint2 bh[4], bl[4];
        #pragma unroll
        for (int mt = 0; mt < 4; mt++) {
            size_t idx = (size_t)(aSlot0 + mt * 256 + s * 32) * 4;
            ah[mt] = *reinterpret_cast<const uint4*>(&g_Ah[idx]);
            al[mt] = *reinterpret_cast<const uint4*>(&g_Al[idx]);
        }
        #pragma unroll
        for (int nt = 0; nt < 4; nt++) {
            size_t idx = (size_t)(bSlot0 + nt * 256 + s * 32) * 2;
            bh[nt] = *reinterpret_cast<const uint2*>(&g_Bh[idx]);
            bl[nt] = *reinterpret_cast<const uint2*>(&g_Bl[idx]);
        }
        #pragma unroll
        for (int mt = 0; mt < 4; mt++)
            #pragma unroll
            for (int nt = 0; nt < 4; nt++) {
                mma_f16(c[mt][nt], ah[mt], bh[nt]);
                mma_f16(c[mt][nt], ah[mt], bl[nt]);
                mma_f16(c[mt][nt], al[mt], bh[nt]);
            }
    }

    // ---------------- epilogue (verified) ----------------
    int trow[8], tcol[8];
    #pragma unroll
    for (int mt = 0; mt < 4; mt++)
        #pragma unroll
        for (int h = 0; h < 2; h++)
            trow[mt * 2 + h] = g_t8[rowBase + wr * 64 + mt * 16 + g + 8 * h];
    #pragma unroll
    for (int nt = 0; nt < 4; nt++)
        #pragma unroll
        for (int p = 0; p < 2; p++)
            tcol[nt * 2 + p] = g_t8[colBase + wc * 32 + nt * 8 + q * 2 + p];

    float rMin[8], rMax[8], cMin[8], cMax[8];
    #pragma unroll
    for (int k = 0; k < 8; k++) { rMin[k] = BIGF; rMax[k] = -BIGF; cMin[k] = BIGF; cMax[k] = -BIGF; }
    #pragma unroll
    for (int mt = 0; mt < 4; mt++)
        #pragma unroll
        for (int nt = 0; nt < 4; nt++)
            #pragma unroll
            for (int r = 0; r < 4; r++) {
                int h = r >> 1, p = r & 1;
                float s = c[mt][nt][r];
                if (trow[mt * 2 + h] == tcol[nt * 2 + p]) {
                    if (s < 1.0f) {
                        rMin[mt * 2 + h] = fminf(rMin[mt * 2 + h], s);
                        cMin[nt * 2 + p] = fminf(cMin[nt * 2 + p], s);
                    }
                } else {
                    rMax[mt * 2 + h] = fmaxf(rMax[mt * 2 + h], s);
                    cMax[nt * 2 + p] = fmaxf(cMax[nt * 2 + p], s);
                }
            }

    #pragma unroll
    for (int o = 1; o <= 2; o <<= 1)
        #pragma unroll
        for (int k = 0; k < 8; k++) {
            rMin[k] = fminf(rMin[k], __shfl_xor_sync(0xFFFFFFFFu, rMin[k], o));
            rMax[k] = fmaxf(rMax[k], __shfl_xor_sync(0xFFFFFFFFu, rMax[k], o));
        }
    if (q == 0) {
        #pragma unroll
        for (int k = 0; k < 8; k++) {
            int row = rowBase + wr * 64 + (k >> 1) * 16 + g + 8 * (k & 1);
            atomicMax(&g_eminpos[row], f2u(-rMin[k]));
            atomicMax(&g_emaxneg[row], f2u(rMax[k]));
        }
    }
    #pragma unroll
    for (int o = 4; o <= 16; o <<= 1)
        #pragma unroll
        for (int k = 0; k < 8; k++) {
            cMin[k] = fminf(cMin[k], __shfl_xor_sync(0xFFFFFFFFu, cMin[k], o));
            cMax[k] = fmaxf(cMax[k], __shfl_xor_sync(0xFFFFFFFFu, cMax[k], o));
        }
    if (g == 0) {
        #pragma unroll
        for (int k = 0; k < 8; k++) {
            int col = colBase + wc * 32 + (k >> 1) * 8 + q * 2 + (k & 1);
            atomicMax(&g_eminpos[col], f2u(-cMin[k]));
            atomicMax(&g_emaxneg[col], f2u(cMax[k]));
        }
    }

    float* S = sm + w * 1152;
    #pragma unroll
    for (int h2 = 0; h2 < 2; h2++) {
        #pragma unroll
        for (int mt2 = 0; mt2 < 2; mt2++) {
            int mt = h2 * 2 + mt2;
            #pragma unroll
            for (int nt = 0; nt < 4; nt++)
                #pragma unroll
                for (int r = 0; r < 4; r++)
                    S[(mt2 * 16 + g + 8 * (r >> 1)) * 36 + nt * 8 + q * 2 + (r & 1)] = c[mt][nt][r];
        }
        __syncwarp();
        #pragma unroll
        for (int pass = 0; pass < 8; pass++) {
            int idx = pass * 32 + lane;
            int lr = idx >> 3, qq = idx & 7;
            float4 v = *reinterpret_cast<const float4*>(&S[lr * 36 + qq * 4]);
            *reinterpret_cast<float4*>(
                &g_sim[(size_t)(rowBase + wr * 64 + h2 * 32 + lr) * N + colBase + wc * 32 + qq * 4]) = v;
        }
        __syncwarp();
        #pragma unroll
        for (int mt2 = 0; mt2 < 2; mt2++) {
            int mt = h2 * 2 + mt2;
            #pragma unroll
            for (int nt = 0; nt < 4; nt++)
                #pragma unroll
                for (int r = 0; r < 4; r++)
                    S[(nt * 8 + q * 2 + (r & 1)) * 36 + mt2 * 16 + g + 8 * (r >> 1)] = c[mt][nt][r];
        }
        __syncwarp();
        #pragma unroll
        for (int pass = 0; pass < 8; pass++) {
            int idx = pass * 32 + lane;
            int lr = idx >> 3, qq = idx & 7;
            float4 v = *reinterpret_cast<const float4*>(&S[lr * 36 + qq * 4]);
            *reinterpret_cast<float4*>(
                &g_sim[(size_t)(colBase + wc * 32 + lr) * N + rowBase + wr * 64 + h2 * 32 + qq * 4]) = v;
        }
        __syncwarp();
    }
}

// ---------------- k_mine: mining (branchless, single ex2) + loss accumulation ----------------
// Warp-per-row: 512 blocks x 256 threads; 4 chunks x 8 front-batched LDG.128 (MLP=8, R14 shape);
// warp-only reduction; single wave.
__global__ __launch_bounds__(256) void k_mine(const float* __restrict__ margin,
                                              const float* __restrict__ weight,
                                              float* __restrict__ out, int out_size) {
    const int lane = threadIdx.x & 31;
    const int warp = threadIdx.x >> 5;
    const int row  = blockIdx.x * 8 + warp;

    const float4* srow4 = reinterpret_cast<const float4*>(&g_sim[(size_t)row * N]);
    const uchar4* t4    = reinterpret_cast<const uchar4*>(g_t8);

    const int   tr = g_t8[row];
    const float m  = margin[row];
    const float wt = weight[row];
    unsigned um = g_eminpos[row];
    unsigned ux = g_emaxneg[row];
    const float minp = um ? -u2f(um) : BIGF;
    const float maxn = ux ? u2f(ux) : -BIGF;

    const float kn = ALPHA * wt * LOG2E, cn = -ALPHA * BASE * LOG2E;
    const float kp = -BETA * wt * LOG2E, cp = BETA * BASE * LOG2E;

    float ps = 0.f, ns = 0.f;
    int ap = 0, an = 0;

    // single ex2 with coefficient select: value identical to the taken path
    #define PROC(S, TJ)                                                     \
        do {                                                                \
            float s_ = (S);                                                 \
            bool isP = ((int)(TJ) == tr);                                   \
            float e = ex2(fmaf(s_, isP ? kp : kn, isP ? cp : cn));          \
            bool pc = isP && (s_ < 1.0f) && ((maxn - s_) + m > 0.0f);       \
            bool nc = (!isP) && (((s_ + m) - minp) > 0.0f);                 \
            ps += pc ? e : 0.0f;                                            \
            ns += nc ? e : 0.0f;                                            \
            ap += pc;                                                       \
            an += nc;                                                       \
        } while (0)

    #pragma unroll
    for (int cch = 0; cch < 4; cch++) {
        float4 s[8];
        uchar4 t[8];
        #pragma unroll
        for (int i = 0; i < 8; i++) {
            int idx = cch * 256 + i * 32 + lane;
            s[i] = srow4[idx];
            t[i] = t4[idx];
        }
        #pragma unroll
        for (int i = 0; i < 8; i++) {
            PROC(s[i].x, t[i].x);
            PROC(s[i].y, t[i].y);
            PROC(s[i].z, t[i].z);
            PROC(s[i].w, t[i].w);
        }
    }
    #undef PROC

    #pragma unroll
    for (int o = 16; o >= 1; o >>= 1) {
        ps += __shfl_xor_sync(0xFFFFFFFFu, ps, o);
        ns += __shfl_xor_sync(0xFFFFFFFFu, ns, o);
        ap += __shfl_xor_sync(0xFFFFFFFFu, ap, o);
        an += __shfl_xor_sync(0xFFFFFFFFu, an, o);
    }

    if (lane == 0) {
        int valid = (ap + an) >= 1;
        float li = valid ? ((2.0f / BETA) * log1pf(ps) + (2.0f / ALPHA) * log1pf(ns)) : 0.0f;
        if (out_size >= 1) atomicAdd(out, li * (1.0f / (float)N));
        if (out_size >= 1 + 2 * N) {
            out[1 + row]     = valid ? (float)ap : 0.0f;
            out[1 + N + row] = valid ? (float)an : 0.0f;
        }
    }
}

// ---------------- launch ----------------
extern "C" void kernel_launch(void* const* d_in, const int* in_sizes, int n_in,
                              void* d_out, int out_size) {
    const float* X      = (const float*)d_in[0];
    const int*   tgt    = (const int*)d_in[1];
    const float* margin = (const float*)d_in[2];
    const float* weight = (const float*)d_in[3];
    float* out = (float*)d_out;

    k_cvt<<<2049, 256>>>(X, tgt, out, out_size);
    k_gemm<<<528, 256>>>();
    k_mine<<<512, 256>>>(margin, weight, out, out_size);
}